// round 15
// baseline (speedup 1.0000x reference)
#include <cuda_runtime.h>
#include <cuda_fp16.h>
#include <math.h>
#include <stdint.h>

// Problem dims (fixed by dataset)
constexpr int BATCH = 8192;
constexpr int DIM   = 1024;
constexpr int HID   = 256;
constexpr long long ED = (long long)BATCH * DIM;  // expert stride (floats)

// Fused GEMM1+gate tiling: fp16 Markidis 3-term, full-HID CTA, 512 threads
constexpr int BM = 64;
constexpr int BN = 256;           // = HID
constexpr int BK = 32;
constexpr int NT = 8192 / BK;     // 256 k-tiles
constexpr int STAGES = 3;
constexpr int NTHREADS = 512;     // 16 warps -> 4 per SMSP

constexpr float LO_SCALE   = 16384.0f;   // 2^14 (keeps B residuals normal in fp16)
constexpr float LO_DESCALE = 1.0f / 16384.0f;

constexpr int AST = 36;                   // A smem stride (floats)
constexpr int BST = 264;                  // B smem stride (u32/half2); 264 % 32 == 8
constexpr int A_FLOATS = BM * AST;        // 2304
constexpr int BP_U32   = 16 * BST;        // 4224 per plane (hi / lo)
constexpr int STAGE_FLOATS = A_FLOATS + 2 * BP_U32;    // 10752
constexpr int SMEM_SZ = STAGES * STAGE_FLOATS * 4;     // 129024
constexpr int HST = 264;                  // h tile smem stride (floats)

// pre-converted W1: [ktile(256)][ hi[16][264] | lo*2^14 [16][264] ] half2
constexpr int BT_U32 = 2 * BP_U32;        // 8448 per ktile
__device__ uint32_t g_Bf16[(size_t)256 * BT_U32];

// ---------------- helpers ----------------
// pack {lo (k-even), hi (k-odd)} -> f16x2
__device__ __forceinline__ uint32_t h2pk(float lo, float hi) {
    uint32_t r;
    asm("cvt.rn.f16x2.f32 %0, %1, %2;" : "=r"(r) : "f"(hi), "f"(lo));
    return r;
}
__device__ __forceinline__ float2 h2up(uint32_t v) {
    float lo, hi;
    asm("{ .reg .f16 l, h; mov.b32 {l, h}, %2;\n\t"
        "  cvt.f32.f16 %0, l; cvt.f32.f16 %1, h; }"
        : "=f"(lo), "=f"(hi) : "r"(v));
    return make_float2(lo, hi);
}
__device__ __forceinline__ float gelu_exact(float x) {
    return 0.5f * x * (1.0f + erff(x * 0.70710678118654752f));
}
__device__ __forceinline__ void cpasync16(void* dst, const void* src) {
    uint32_t d;
    asm("{ .reg .u64 t; cvta.to.shared.u64 t, %1; cvt.u32.u64 %0, t; }"
        : "=r"(d) : "l"(dst));
    asm volatile("cp.async.cg.shared.global [%0], [%1], 16;"
                 :: "r"(d), "l"(src) : "memory");
}
__device__ __forceinline__ void mma_f16(float* c, const uint32_t* a, const uint32_t* b) {
    asm volatile(
        "mma.sync.aligned.m16n8k16.row.col.f32.f16.f16.f32 "
        "{%0,%1,%2,%3}, {%4,%5,%6,%7}, {%8,%9}, {%0,%1,%2,%3};"
        : "+f"(c[0]), "+f"(c[1]), "+f"(c[2]), "+f"(c[3])
        : "r"(a[0]), "r"(a[1]), "r"(a[2]), "r"(a[3]), "r"(b[0]), "r"(b[1]));
}

// ---------------- prep: W1 -> fp16 hi plane + scaled residual plane ----------------
__global__ void __launch_bounds__(256) prep_w1(const float* __restrict__ W1) {
    const int idx = blockIdx.x * 256 + threadIdx.x;   // one per (k-pair, n)
    const int n  = idx & 255;
    const int k2 = idx >> 8;             // 0..4095
    const float x0 = W1[(size_t)(2 * k2)     * HID + n];
    const float x1 = W1[(size_t)(2 * k2 + 1) * HID + n];
    const int kt  = k2 >> 4;
    const int row = k2 & 15;

    const uint32_t h = h2pk(x0, x1);
    const float2 hf = h2up(h);
    const uint32_t l = h2pk((x0 - hf.x) * LO_SCALE, (x1 - hf.y) * LO_SCALE);

    uint32_t* bf = g_Bf16 + (size_t)kt * BT_U32;
    bf[row * BST + n]           = h;
    bf[BP_U32 + row * BST + n]  = l;
}

// ---------------- fused GEMM1 + GELU + gate + top2 + combine ----------------
__global__ void __launch_bounds__(NTHREADS, 1)
moe_fused(const float* __restrict__ zs, const float* __restrict__ b1,
          const float* __restrict__ W2, const float* __restrict__ b2,
          float* __restrict__ fused, float* __restrict__ wout)
{
    extern __shared__ float smem[];
    const int tid  = threadIdx.x;
    const int lane = tid & 31;
    const int wid  = tid >> 5;         // 0..15
    const int wm   = wid & 1;          // 2 warps along M (32 rows each)
    const int wn   = wid >> 1;         // 8 warps along N (32 cols each)
    const int brow = blockIdx.x * BM;

    auto copy_tile = [&](int kt, int s) {
        float*    As = smem + (size_t)s * STAGE_FLOATS;
        uint32_t* Bf = (uint32_t*)(As + A_FLOATS);
        const int k0 = kt * BK;
        const int e  = k0 >> 10;
        const float* abase = zs + (size_t)e * ED + (k0 & 1023);
        // A: 64 rows x 32 floats = 512 chunks (1 per thread)
        {
            const int r  = tid >> 3;
            const int kc = tid & 7;
            cpasync16(As + r * AST + kc * 4,
                      abase + (size_t)(brow + r) * DIM + kc * 4);
        }
        // B: identity copy of padded image (2112 chunks)
        const uint32_t* gbf = g_Bf16 + (size_t)kt * BT_U32;
        #pragma unroll
        for (int i = 0; i < 5; i++) {
            const int c = tid + i * NTHREADS;
            if (c < BT_U32 / 4) cpasync16(Bf + c * 4, gbf + c * 4);
        }
        asm volatile("cp.async.commit_group;" ::: "memory");
    };

    float accA[2][4][4];   // Ah*Bh + Al*Bh  (unscaled)
    float accB[2][4][4];   // Ah*Bl'         (scale 2^14)
    #pragma unroll
    for (int i = 0; i < 2; i++)
        #pragma unroll
        for (int j = 0; j < 4; j++)
            #pragma unroll
            for (int q = 0; q < 4; q++) { accA[i][j][q] = 0.0f; accB[i][j][q] = 0.0f; }

    copy_tile(0, 0);
    copy_tile(1, 1);

    const int l4  = lane & 3;
    const int ld4 = lane >> 2;

    for (int kt = 0; kt < NT; kt++) {
        asm volatile("cp.async.wait_group %0;" :: "n"(STAGES - 2) : "memory");
        __syncthreads();
        if (kt + STAGES - 1 < NT)
            copy_tile(kt + STAGES - 1, (kt + STAGES - 1) % STAGES);
        else
            asm volatile("cp.async.commit_group;" ::: "memory");

        const float*    As = smem + (size_t)(kt % STAGES) * STAGE_FLOATS;
        const uint32_t* Bf = (const uint32_t*)(As + A_FLOATS);

        #pragma unroll
        for (int s = 0; s < 2; s++) {
            // A fragments for both mt, this k16 step
            uint32_t ah[2][4], al[2][4];
            #pragma unroll
            for (int mt = 0; mt < 2; mt++) {
                const int m  = wm * 32 + mt * 16 + ld4;
                const int kk = s * 16 + 2 * l4;
                const float2 xa = *(const float2*)&As[m       * AST + kk];
                const float2 xb = *(const float2*)&As[(m + 8) * AST + kk];
                const float2 xc = *(const float2*)&As[m       * AST + kk + 8];
                const float2 xd = *(const float2*)&As[(m + 8) * AST + kk + 8];
                ah[mt][0] = h2pk(xa.x, xa.y);
                ah[mt][1] = h2pk(xb.x, xb.y);
                ah[mt][2] = h2pk(xc.x, xc.y);
                ah[mt][3] = h2pk(xd.x, xd.y);
                const float2 fa = h2up(ah[mt][0]);
                const float2 fb = h2up(ah[mt][1]);
                const float2 fc = h2up(ah[mt][2]);
                const float2 fd = h2up(ah[mt][3]);
                al[mt][0] = h2pk(xa.x - fa.x, xa.y - fa.y);
                al[mt][1] = h2pk(xb.x - fb.x, xb.y - fb.y);
                al[mt][2] = h2pk(xc.x - fc.x, xc.y - fc.y);
                al[mt][3] = h2pk(xd.x - fd.x, xd.y - fd.y);
            }
            #pragma unroll
            for (int nt = 0; nt < 4; nt++) {
                const int n  = wn * 32 + nt * 8 + ld4;
                const int r0 = s * 8 + l4;
                uint32_t bH[2], bL[2];
                bH[0] = Bf[r0 * BST + n];
                bH[1] = Bf[(r0 + 4) * BST + n];
                bL[0] = Bf[BP_U32 + r0 * BST + n];
                bL[1] = Bf[BP_U32 + (r0 + 4) * BST + n];
                mma_f16(accA[0][nt], ah[0], bH);
                mma_f16(accA[1][nt], ah[1], bH);
                mma_f16(accA[0][nt], al[0], bH);
                mma_f16(accA[1][nt], al[1], bH);
                mma_f16(accB[0][nt], ah[0], bL);
                mma_f16(accB[1][nt], ah[1], bL);
            }
        }
    }

    // ---------------- epilogue ----------------
    __syncthreads();                       // everyone done with stage buffers
    float* ht = smem;                      // h tile [64][HST]

    #pragma unroll
    for (int mt = 0; mt < 2; mt++) {
        const int r0 = wm * 32 + mt * 16 + ld4;
        #pragma unroll
        for (int nt = 0; nt < 4; nt++) {
            const int cg = wn * 32 + nt * 8 + 2 * l4;
            const float bx = b1[cg], by = b1[cg + 1];
            float2 o0, o1;
            o0.x = gelu_exact(accA[mt][nt][0] + accB[mt][nt][0] * LO_DESCALE + bx);
            o0.y = gelu_exact(accA[mt][nt][1] + accB[mt][nt][1] * LO_DESCALE + by);
            o1.x = gelu_exact(accA[mt][nt][2] + accB[mt][nt][2] * LO_DESCALE + bx);
            o1.y = gelu_exact(accA[mt][nt][3] + accB[mt][nt][3] * LO_DESCALE + by);
            *(float2*)&ht[r0 * HST + cg]       = o0;
            *(float2*)&ht[(r0 + 8) * HST + cg] = o1;
        }
    }
    __syncthreads();

    // gate + top2 + combine: warp wid handles rows wid*4 .. wid*4+3
    for (int r = 0; r < 4; r++) {
        const int row_l = wid * 4 + r;
        const int row   = brow + row_l;
        const float* hrow = ht + (size_t)row_l * HST;

        float acc[8] = {0.f, 0.f, 0.f, 0.f, 0.f, 0.f, 0.f, 0.f};
        #pragma unroll
        for (int kk = 0; kk < 8; kk++) {
            const int k = kk * 32 + lane;
            const float hv = hrow[k];
            const float4 wa = *(const float4*)(W2 + (size_t)k * 8);
            const float4 wb = *(const float4*)(W2 + (size_t)k * 8 + 4);
            acc[0] += hv * wa.x; acc[1] += hv * wa.y;
            acc[2] += hv * wa.z; acc[3] += hv * wa.w;
            acc[4] += hv * wb.x; acc[5] += hv * wb.y;
            acc[6] += hv * wb.z; acc[7] += hv * wb.w;
        }
        #pragma unroll
        for (int m = 0; m < 8; m++) {
            #pragma unroll
            for (int s = 16; s > 0; s >>= 1)
                acc[m] += __shfl_xor_sync(0xffffffffu, acc[m], s);
            acc[m] += b2[m];
        }

        // top-2, jax tie-break (lower index wins -> strict >)
        int i1 = 0; float l1 = acc[0];
        #pragma unroll
        for (int m = 1; m < 8; m++) if (acc[m] > l1) { l1 = acc[m]; i1 = m; }
        int i2 = (i1 == 0) ? 1 : 0; float l2 = acc[i2];
        #pragma unroll
        for (int m = 0; m < 8; m++)
            if (m != i1 && m != ((i1 == 0) ? 1 : 0) && acc[m] > l2) { l2 = acc[m]; i2 = m; }

        const float e2  = expf(l2 - l1);
        const float inv = 1.0f / (1.0f + e2);
        const float w1  = inv;
        const float w2v = e2 * inv;

        if (lane < 8)
            wout[(size_t)row * 8 + lane] =
                (lane == i1) ? w1 : ((lane == i2) ? w2v : 0.0f);

        const float4* z1 = (const float4*)(zs + (size_t)i1 * ED + (size_t)row * DIM);
        const float4* z2 = (const float4*)(zs + (size_t)i2 * ED + (size_t)row * DIM);
        float4* fo = (float4*)(fused + (size_t)row * DIM);
        #pragma unroll
        for (int v = 0; v < 8; v++) {
            const int idx = v * 32 + lane;
            const float4 A  = z1[idx];
            const float4 Bv = z2[idx];
            float4 o;
            o.x = w1 * A.x + w2v * Bv.x;
            o.y = w1 * A.y + w2v * Bv.y;
            o.z = w1 * A.z + w2v * Bv.z;
            o.w = w1 * A.w + w2v * Bv.w;
            fo[idx] = o;
        }
    }
}

extern "C" void kernel_launch(void* const* d_in, const int* in_sizes, int n_in,
                              void* d_out, int out_size)
{
    const float* zs = (const float*)d_in[0];
    const float* W1 = (const float*)d_in[1];
    const float* b1 = (const float*)d_in[2];
    const float* W2 = (const float*)d_in[3];
    const float* b2 = (const float*)d_in[4];

    float* out   = (float*)d_out;
    float* fused = out;                        // [B, D]
    float* wout  = out + (size_t)BATCH * DIM;  // [B, M]

    cudaFuncSetAttribute(moe_fused, cudaFuncAttributeMaxDynamicSharedMemorySize, SMEM_SZ);

    prep_w1<<<(4096 * 256) / 256, 256>>>(W1);
    moe_fused<<<BATCH / BM, NTHREADS, SMEM_SZ>>>(zs, b1, W2, b2, fused, wout);
}

// round 17
// speedup vs baseline: 1.8918x; 1.8918x over previous
#include <cuda_runtime.h>
#include <cuda_fp16.h>
#include <math.h>
#include <stdint.h>

// Problem dims (fixed by dataset)
constexpr int BATCH = 8192;
constexpr int DIM   = 1024;
constexpr int HID   = 256;
constexpr long long ED = (long long)BATCH * DIM;  // expert stride (floats)

constexpr int BM = 64;
constexpr int BN = 256;           // = HID
constexpr int BK = 32;
constexpr int NT = 8192 / BK;     // 256 k-tiles
constexpr int NTHREADS = 512;     // 16 warps

constexpr float LO_SCALE   = 16384.0f;   // 2^14 for B residual plane
constexpr float LO_DESCALE = 1.0f / 16384.0f;

// smem layout (bytes):
//  stage s (s=0..2) at s*STAGE_B: [ B frag image 40960 | A fp32 9216 ]
//  A fp16 planes at AF16_OFF: Ah[64][20]u32 (5120 B) | Al (5120 B)
constexpr int B_STAGE_B  = 40960;            // 2*8*32*20 u32
constexpr int A32_B      = 9216;             // 64 * 36 floats
constexpr int STAGE_B    = B_STAGE_B + A32_B;   // 50176
constexpr int AF16_OFF   = 3 * STAGE_B;         // 150528
constexpr int A16_ROW_U32 = 20;              // 80 B/row: 16B-aligned + conflict-free
constexpr int A16_PLANE_U32 = 64 * A16_ROW_U32;   // 1280
constexpr int SMEM_SZ    = AF16_OFF + 2 * A16_PLANE_U32 * 4;  // 160768
constexpr int HST = 264;                     // h tile stride (floats); 64*264*4=67584 fits

// pre-packed W1 frag image: per ktile 10240 u32 (lane block of 16 padded to 20)
__device__ uint32_t g_B[(size_t)256 * 10240];

// ---------------- helpers ----------------
__device__ __forceinline__ uint32_t smem_u32(const void* p) {
    uint32_t a;
    asm("{ .reg .u64 t; cvta.to.shared.u64 t, %1; cvt.u32.u64 %0, t; }"
        : "=r"(a) : "l"(p));
    return a;
}
__device__ __forceinline__ uint32_t h2pk(float lo, float hi) {
    uint32_t r;
    asm("cvt.rn.f16x2.f32 %0, %1, %2;" : "=r"(r) : "f"(hi), "f"(lo));
    return r;
}
__device__ __forceinline__ float2 h2up(uint32_t v) {
    float lo, hi;
    asm("{ .reg .f16 l, h; mov.b32 {l, h}, %2;\n\t"
        "  cvt.f32.f16 %0, l; cvt.f32.f16 %1, h; }"
        : "=f"(lo), "=f"(hi) : "r"(v));
    return make_float2(lo, hi);
}
__device__ __forceinline__ float gelu_exact(float x) {
    return 0.5f * x * (1.0f + erff(x * 0.70710678118654752f));
}
__device__ __forceinline__ void cpasync16(void* dst, const void* src) {
    uint32_t d;
    asm("{ .reg .u64 t; cvta.to.shared.u64 t, %1; cvt.u32.u64 %0, t; }"
        : "=r"(d) : "l"(dst));
    asm volatile("cp.async.cg.shared.global [%0], [%1], 16;"
                 :: "r"(d), "l"(src) : "memory");
}
__device__ __forceinline__ void mma_f16(float* c, const uint32_t* a, const uint32_t* b) {
    asm volatile(
        "mma.sync.aligned.m16n8k16.row.col.f32.f16.f16.f32 "
        "{%0,%1,%2,%3}, {%4,%5,%6,%7}, {%8,%9}, {%0,%1,%2,%3};"
        : "+f"(c[0]), "+f"(c[1]), "+f"(c[2]), "+f"(c[3])
        : "r"(a[0]), "r"(a[1]), "r"(a[2]), "r"(a[3]), "r"(b[0]), "r"(b[1]));
}
__device__ __forceinline__ void ldm_x4(uint32_t* r, uint32_t addr) {
    asm volatile("ldmatrix.sync.aligned.m8n8.x4.shared.b16 {%0,%1,%2,%3}, [%4];"
        : "=r"(r[0]), "=r"(r[1]), "=r"(r[2]), "=r"(r[3]) : "r"(addr));
}
__device__ __forceinline__ void lds128(uint32_t* r, uint32_t addr) {
    asm volatile("ld.shared.v4.u32 {%0,%1,%2,%3}, [%4];"
        : "=r"(r[0]), "=r"(r[1]), "=r"(r[2]), "=r"(r[3]) : "r"(addr));
}

// ---------------- prep: W1 -> fragment-ordered fp16 image ----------------
// one thread per frag u32: [kt(256)][s(2)][wn(8)][lane(32)][j(16)]; lane block padded to 20
__global__ void __launch_bounds__(256) prep_w1(const float* __restrict__ W1) {
    const int idx  = blockIdx.x * 256 + threadIdx.x;
    const int j    = idx & 15;
    const int lane = (idx >> 4) & 31;
    const int wn   = (idx >> 9) & 7;
    const int s    = (idx >> 12) & 1;
    const int kt   = idx >> 13;
    const int nt    = (j >> 1) & 3;
    const int which = j & 1;
    const int plane = j >> 3;

    const int n = wn * 32 + nt * 8 + (lane >> 2);
    const int k = kt * 32 + s * 16 + ((lane & 3) << 1) + (which << 3);
    const float x0 = W1[(size_t)k * HID + n];
    const float x1 = W1[(size_t)(k + 1) * HID + n];

    uint32_t val;
    if (plane == 0) {
        val = h2pk(x0, x1);
    } else {
        const uint32_t h = h2pk(x0, x1);
        const float2 f = h2up(h);
        val = h2pk((x0 - f.x) * LO_SCALE, (x1 - f.y) * LO_SCALE);
    }
    g_B[((size_t)kt * 512 + ((s * 8 + wn) * 32 + lane)) * 20 + j] = val;
}

// ---------------- fused GEMM1 + GELU + gate + top2 + combine ----------------
__global__ void __launch_bounds__(NTHREADS, 1)
moe_fused(const float* __restrict__ zs, const float* __restrict__ b1,
          const float* __restrict__ W2, const float* __restrict__ b2,
          float* __restrict__ fused, float* __restrict__ wout)
{
    extern __shared__ char smem_c[];
    const uint32_t sbase = smem_u32(smem_c);
    const int tid  = threadIdx.x;
    const int lane = tid & 31;
    const int wid  = tid >> 5;         // 0..15
    const int wm   = wid & 1;          // 2 warps along M (32 rows)
    const int wn   = wid >> 1;         // 8 warps along N (32 cols)
    const int brow = blockIdx.x * BM;

    auto copy_tile = [&](int kt, int s) {
        char* sb = smem_c + s * STAGE_B;
        uint32_t* Bd = (uint32_t*)sb;
        float*    Ad = (float*)(sb + B_STAGE_B);
        // B: 2560 16B-chunks, 5 per thread
        const uint32_t* gB = g_B + (size_t)kt * 10240;
        #pragma unroll
        for (int i = 0; i < 5; i++) {
            const int c = tid + i * NTHREADS;
            cpasync16(Bd + c * 4, gB + c * 4);
        }
        // A fp32: 512 chunks, 1 per thread
        const int k0 = kt * BK;
        const float* abase = zs + (size_t)(k0 >> 10) * ED + (k0 & 1023);
        const int r  = tid >> 3;
        const int kc = tid & 7;
        cpasync16(Ad + r * 36 + kc * 4,
                  abase + (size_t)(brow + r) * DIM + kc * 4);
        asm volatile("cp.async.commit_group;" ::: "memory");
    };

    float accA[2][4][4];   // Ah*Bh + Al*Bh
    float accB[2][4][4];   // Ah*Bl' (scale 2^14)
    #pragma unroll
    for (int i = 0; i < 2; i++)
        #pragma unroll
        for (int j = 0; j < 4; j++)
            #pragma unroll
            for (int q = 0; q < 4; q++) { accA[i][j][q] = 0.0f; accB[i][j][q] = 0.0f; }

    copy_tile(0, 0);
    copy_tile(1, 1);

    // per-lane ldmatrix base (A fp16 planes, 80 B row stride -> 16B aligned)
    const uint32_t a_base = sbase + AF16_OFF
                          + (wm * 32 + (lane & 15)) * 80 + ((lane >> 4) << 4);
    const int cvt_m  = tid >> 3;
    const int cvt_kb = (tid & 7) << 2;

    for (int kt = 0; kt < NT; kt++) {
        asm volatile("cp.async.wait_group 1;" ::: "memory");
        __syncthreads();

        // cooperative A fp32 -> fp16 hi/lo planes (each thread one float4)
        {
            const float* As32 = (const float*)(smem_c + (kt % 3) * STAGE_B + B_STAGE_B);
            uint32_t* Ah = (uint32_t*)(smem_c + AF16_OFF);
            uint32_t* Al = Ah + A16_PLANE_U32;
            const float4 v = *(const float4*)(As32 + cvt_m * 36 + cvt_kb);
            const uint32_t h0 = h2pk(v.x, v.y), h1 = h2pk(v.z, v.w);
            const float2 f0 = h2up(h0), f1 = h2up(h1);
            const uint32_t l0 = h2pk(v.x - f0.x, v.y - f0.y);
            const uint32_t l1 = h2pk(v.z - f1.x, v.w - f1.y);
            *(uint2*)&Ah[cvt_m * A16_ROW_U32 + (cvt_kb >> 1)] = make_uint2(h0, h1);
            *(uint2*)&Al[cvt_m * A16_ROW_U32 + (cvt_kb >> 1)] = make_uint2(l0, l1);
        }
        __syncthreads();

        if (kt + 2 < NT) copy_tile(kt + 2, (kt + 2) % 3);
        else asm volatile("cp.async.commit_group;" ::: "memory");

        const uint32_t Bb = sbase + (kt % 3) * STAGE_B;

        #pragma unroll
        for (int s = 0; s < 2; s++) {
            uint32_t ah[2][4], al[2][4];
            ldm_x4(ah[0], a_base + s * 32);
            ldm_x4(ah[1], a_base + 16 * 80 + s * 32);
            ldm_x4(al[0], a_base + A16_PLANE_U32 * 4 + s * 32);
            ldm_x4(al[1], a_base + A16_PLANE_U32 * 4 + 16 * 80 + s * 32);

            uint32_t bf[16];
            const uint32_t bb = Bb + (((s << 3) + wn) * 32 + lane) * 80;
            lds128(bf + 0,  bb);
            lds128(bf + 4,  bb + 16);
            lds128(bf + 8,  bb + 32);
            lds128(bf + 12, bb + 48);

            // interleave accumulator groups: RAW distance >= 8
            #pragma unroll
            for (int nt = 0; nt < 4; nt++) mma_f16(accA[0][nt], ah[0], bf + 2 * nt);
            #pragma unroll
            for (int nt = 0; nt < 4; nt++) mma_f16(accA[1][nt], ah[1], bf + 2 * nt);
            #pragma unroll
            for (int nt = 0; nt < 4; nt++) mma_f16(accB[0][nt], ah[0], bf + 8 + 2 * nt);
            #pragma unroll
            for (int nt = 0; nt < 4; nt++) mma_f16(accB[1][nt], ah[1], bf + 8 + 2 * nt);
            #pragma unroll
            for (int nt = 0; nt < 4; nt++) mma_f16(accA[0][nt], al[0], bf + 2 * nt);
            #pragma unroll
            for (int nt = 0; nt < 4; nt++) mma_f16(accA[1][nt], al[1], bf + 2 * nt);
        }
    }

    // ---------------- epilogue ----------------
    __syncthreads();                       // all mma done; reuse smem
    float* ht = (float*)smem_c;            // h tile [64][HST]
    const int l4  = lane & 3;
    const int ld4 = lane >> 2;

    #pragma unroll
    for (int mt = 0; mt < 2; mt++) {
        const int r0 = wm * 32 + mt * 16 + ld4;
        #pragma unroll
        for (int nt = 0; nt < 4; nt++) {
            const int cg = wn * 32 + nt * 8 + 2 * l4;
            const float bx = b1[cg], by = b1[cg + 1];
            float2 o0, o1;
            o0.x = gelu_exact(accA[mt][nt][0] + accB[mt][nt][0] * LO_DESCALE + bx);
            o0.y = gelu_exact(accA[mt][nt][1] + accB[mt][nt][1] * LO_DESCALE + by);
            o1.x = gelu_exact(accA[mt][nt][2] + accB[mt][nt][2] * LO_DESCALE + bx);
            o1.y = gelu_exact(accA[mt][nt][3] + accB[mt][nt][3] * LO_DESCALE + by);
            *(float2*)&ht[r0 * HST + cg]       = o0;
            *(float2*)&ht[(r0 + 8) * HST + cg] = o1;
        }
    }
    __syncthreads();

    // gate + top2 + combine: warp wid handles rows wid*4 .. wid*4+3
    for (int r = 0; r < 4; r++) {
        const int row_l = wid * 4 + r;
        const int row   = brow + row_l;
        const float* hrow = ht + (size_t)row_l * HST;

        float acc[8] = {0.f, 0.f, 0.f, 0.f, 0.f, 0.f, 0.f, 0.f};
        #pragma unroll
        for (int kk = 0; kk < 8; kk++) {
            const int k = kk * 32 + lane;
            const float hv = hrow[k];
            const float4 wa = *(const float4*)(W2 + (size_t)k * 8);
            const float4 wb = *(const float4*)(W2 + (size_t)k * 8 + 4);
            acc[0] += hv * wa.x; acc[1] += hv * wa.y;
            acc[2] += hv * wa.z; acc[3] += hv * wa.w;
            acc[4] += hv * wb.x; acc[5] += hv * wb.y;
            acc[6] += hv * wb.z; acc[7] += hv * wb.w;
        }
        #pragma unroll
        for (int m = 0; m < 8; m++) {
            #pragma unroll
            for (int s = 16; s > 0; s >>= 1)
                acc[m] += __shfl_xor_sync(0xffffffffu, acc[m], s);
            acc[m] += b2[m];
        }

        // top-2, jax tie-break (lower index wins -> strict >)
        int i1 = 0; float l1 = acc[0];
        #pragma unroll
        for (int m = 1; m < 8; m++) if (acc[m] > l1) { l1 = acc[m]; i1 = m; }
        int i2 = (i1 == 0) ? 1 : 0; float l2 = acc[i2];
        #pragma unroll
        for (int m = 0; m < 8; m++)
            if (m != i1 && m != ((i1 == 0) ? 1 : 0) && acc[m] > l2) { l2 = acc[m]; i2 = m; }

        const float e2  = expf(l2 - l1);
        const float inv = 1.0f / (1.0f + e2);
        const float w1  = inv;
        const float w2v = e2 * inv;

        if (lane < 8)
            wout[(size_t)row * 8 + lane] =
                (lane == i1) ? w1 : ((lane == i2) ? w2v : 0.0f);

        const float4* z1 = (const float4*)(zs + (size_t)i1 * ED + (size_t)row * DIM);
        const float4* z2 = (const float4*)(zs + (size_t)i2 * ED + (size_t)row * DIM);
        float4* fo = (float4*)(fused + (size_t)row * DIM);
        #pragma unroll
        for (int v = 0; v < 8; v++) {
            const int idx = v * 32 + lane;
            const float4 A  = z1[idx];
            const float4 Bv = z2[idx];
            float4 o;
            o.x = w1 * A.x + w2v * Bv.x;
            o.y = w1 * A.y + w2v * Bv.y;
            o.z = w1 * A.z + w2v * Bv.z;
            o.w = w1 * A.w + w2v * Bv.w;
            fo[idx] = o;
        }
    }
}

extern "C" void kernel_launch(void* const* d_in, const int* in_sizes, int n_in,
                              void* d_out, int out_size)
{
    const float* zs = (const float*)d_in[0];
    const float* W1 = (const float*)d_in[1];
    const float* b1 = (const float*)d_in[2];
    const float* W2 = (const float*)d_in[3];
    const float* b2 = (const float*)d_in[4];

    float* out   = (float*)d_out;
    float* fused = out;                        // [B, D]
    float* wout  = out + (size_t)BATCH * DIM;  // [B, M]

    cudaFuncSetAttribute(moe_fused, cudaFuncAttributeMaxDynamicSharedMemorySize, SMEM_SZ);

    prep_w1<<<(256 * 2 * 8 * 32 * 16) / 256, 256>>>(W1);
    moe_fused<<<BATCH / BM, NTHREADS, SMEM_SZ>>>(zs, b1, W2, b2, fused, wout);
}